// round 12
// baseline (speedup 1.0000x reference)
#include <cuda_runtime.h>
#include <math.h>

#define B_SZ 32
#define S_SZ 8
#define T_SZ 256
#define IMG_H 128
#define IMG_W 128
#define KS 11
#define OUT_W 118            // 128 - 11 + 1
#define NPIX (OUT_W*OUT_W)   // 13924
#define NIMG 40              // 32 img + 8 sample_img
#define NPAIR 256            // B*S
#define INFV 1e10f
#define C1V 1.0e-4f
#define C2V 9.0e-4f

// -------- scratch (device globals; no runtime allocation) --------
__device__ float g_mu  [NIMG*3*NPIX];   // blurred mean per image-channel
__device__ float g_sxx [NIMG*3*NPIX];   // blur(x^2) - mu^2 per image-channel
__device__ float g_ssim_part[NPAIR*3];  // per (pair,channel) SSIM pixel-sum
__device__ float g_sdtw[NPAIR];         // soft-DTW result per pair

// Gaussian weights computed in double (matches numpy float64 -> f32 path)
__device__ __forceinline__ void make_weights(float* w, int tid) {
    if (tid == 0) {
        double tmp[KS]; double s = 0.0;
        #pragma unroll
        for (int i = 0; i < KS; i++) {
            double t = (i - 5.0) / 1.5;
            tmp[i] = exp(-0.5 * t * t);
            s += tmp[i];
        }
        #pragma unroll
        for (int i = 0; i < KS; i++) w[i] = (float)(tmp[i] / s);
    }
}

// ================= kernel A: per-image-channel blur stats =================
// grid = NIMG*3 blocks, 256 threads
__global__ void stats_kernel(const float* __restrict__ img,
                             const float* __restrict__ simg) {
    extern __shared__ float sh[];
    float* xbuf = sh;                       // 128*128
    float* t1   = xbuf + IMG_H*IMG_W;       // 128*118  (blur_h(x))
    float* t2   = t1   + IMG_H*OUT_W;       // 128*118  (blur_h(x^2))
    __shared__ float w[KS];
    const int tid = threadIdx.x;
    const int n = blockIdx.x / 3;
    const int c = blockIdx.x % 3;
    make_weights(w, tid);

    const float* src = (n < B_SZ)
        ? (img  + ((size_t)n * 3 + c) * (IMG_H*IMG_W))
        : (simg + ((size_t)(n - B_SZ) * 3 + c) * (IMG_H*IMG_W));

    for (int i = tid; i < IMG_H*IMG_W; i += blockDim.x) xbuf[i] = src[i];
    __syncthreads();

    for (int i = tid; i < IMG_H*OUT_W; i += blockDim.x) {
        int r = i / OUT_W, c0 = i % OUT_W;
        const float* row = xbuf + r * IMG_W + c0;
        float a = 0.f, b = 0.f;
        #pragma unroll
        for (int k = 0; k < KS; k++) {
            float v = row[k];
            a = fmaf(w[k], v, a);
            b = fmaf(w[k], v * v, b);
        }
        t1[i] = a; t2[i] = b;
    }
    __syncthreads();

    float* mu_out  = g_mu  + (size_t)blockIdx.x * NPIX;
    float* sxx_out = g_sxx + (size_t)blockIdx.x * NPIX;
    for (int i = tid; i < NPIX; i += blockDim.x) {
        int r = i / OUT_W, c0 = i % OUT_W;
        float a = 0.f, b = 0.f;
        #pragma unroll
        for (int k = 0; k < KS; k++) {
            a = fmaf(w[k], t1[(r + k) * OUT_W + c0], a);
            b = fmaf(w[k], t2[(r + k) * OUT_W + c0], b);
        }
        mu_out[i]  = a;
        sxx_out[i] = b - a * a;
    }
}

// ================= kernel B: per-pair cross blur + SSIM sum =================
// grid = NPAIR*3 blocks, 256 threads. Only blur(x*y) is pair-dependent.
__global__ void ssim_kernel(const float* __restrict__ img,
                            const float* __restrict__ simg) {
    extern __shared__ float sh[];
    float* prod = sh;                     // 128*128
    float* t1   = prod + IMG_H*IMG_W;     // 128*118
    __shared__ float w[KS];
    __shared__ float red[256];
    const int tid = threadIdx.x;
    const int p = blockIdx.x / 3;         // pair index b*S + s
    const int c = blockIdx.x % 3;
    const int b = p / S_SZ;
    const int s = p % S_SZ;
    make_weights(w, tid);

    const float* x = simg + ((size_t)s * 3 + c) * (IMG_H*IMG_W); // X = sample
    const float* y = img  + ((size_t)b * 3 + c) * (IMG_H*IMG_W); // Y = img
    for (int i = tid; i < IMG_H*IMG_W; i += blockDim.x) prod[i] = x[i] * y[i];
    __syncthreads();

    for (int i = tid; i < IMG_H*OUT_W; i += blockDim.x) {
        int r = i / OUT_W, c0 = i % OUT_W;
        const float* row = prod + r * IMG_W + c0;
        float a = 0.f;
        #pragma unroll
        for (int k = 0; k < KS; k++) a = fmaf(w[k], row[k], a);
        t1[i] = a;
    }
    __syncthreads();

    const float* mux_p = g_mu  + (size_t)((B_SZ + s) * 3 + c) * NPIX;
    const float* muy_p = g_mu  + (size_t)(b * 3 + c) * NPIX;
    const float* sxx_p = g_sxx + (size_t)((B_SZ + s) * 3 + c) * NPIX;
    const float* syy_p = g_sxx + (size_t)(b * 3 + c) * NPIX;

    float acc = 0.f;
    for (int i = tid; i < NPIX; i += blockDim.x) {
        int r = i / OUT_W, c0 = i % OUT_W;
        float sb = 0.f;
        #pragma unroll
        for (int k = 0; k < KS; k++) sb = fmaf(w[k], t1[(r + k) * OUT_W + c0], sb);
        float mx = mux_p[i], my = muy_p[i];
        float mxy = mx * my;
        float sxy = sb - mxy;
        float num = (2.f * mxy + C1V) * (2.f * sxy + C2V);
        float den = (mx * mx + my * my + C1V) * (sxx_p[i] + syy_p[i] + C2V);
        acc += num / den;
    }
    red[tid] = acc;
    __syncthreads();
    #pragma unroll
    for (int off = 128; off > 0; off >>= 1) {
        if (tid < off) red[tid] += red[tid + off];
        __syncthreads();
    }
    if (tid == 0) g_ssim_part[blockIdx.x] = red[0];
}

// ================= kernel C: soft-DTW wavefront =================
// grid = NPAIR blocks, T_SZ threads. thread i owns row i; anti-diagonal sweep.
__global__ void sdtw_kernel(const float* __restrict__ input,
                            const float* __restrict__ samples) {
    __shared__ float ybuf[T_SZ];
    __shared__ float diag[3][T_SZ + 1];
    const int p = blockIdx.x;
    const int b = p / S_SZ;
    const int s = p % S_SZ;
    const int i = threadIdx.x;

    const float xi = input[b * T_SZ + i];
    ybuf[i] = samples[s * T_SZ + i];
    diag[0][i] = INFV; diag[1][i] = INFV; diag[2][i] = INFV;
    if (i == 0) { diag[0][T_SZ] = INFV; diag[1][T_SZ] = INFV; diag[2][T_SZ] = INFV; }
    __syncthreads();

    float myPrev = INFV;   // R[i, j-1] = my value from previous diagonal
    #pragma unroll 1
    for (int k = 0; k < 2 * T_SZ - 1; k++) {
        const int cur = k % 3;            // diag k
        const int p1  = (k + 2) % 3;      // diag k-1
        const int p2  = (k + 1) % 3;      // diag k-2
        const int j = k - i;
        const float a  = diag[p2][i];     // R[i-1, j-1]
        const float bb = diag[p1][i];     // R[i-1, j]
        const float cc = myPrev;          // R[i, j-1]
        float m = fminf(fminf(a, bb), cc);
        float e = __expf((m - a) * 100.f) + __expf((m - bb) * 100.f)
                + __expf((m - cc) * 100.f);
        float sm = m - 0.01f * __logf(e);
        if (k == 0 && i == 0) sm = 0.f;   // base cell R[0,0] = D[0,0]
        float r;
        if (j >= 0 && j < T_SZ) {
            float d = xi - ybuf[j];
            r = fmaf(d, d, sm);
        } else {
            r = INFV;
        }
        diag[cur][i + 1] = r;
        myPrev = r;
        __syncthreads();
    }
    if (i == T_SZ - 1) g_sdtw[p] = myPrev;  // R[T-1, T-1]
}

// ================= kernel D: finalize (metric sum + BCE + loss) =================
__global__ void finalize_kernel(const float* __restrict__ outp,
                                const float* __restrict__ labels,
                                float* __restrict__ out, int out_size) {
    __shared__ float red[256];
    __shared__ float ms_sh;
    const int t = threadIdx.x;

    // per-pair metric: ((1-ssim)*10 + sdtw/500) / 2
    float ss = (g_ssim_part[t * 3] + g_ssim_part[t * 3 + 1] + g_ssim_part[t * 3 + 2])
               * (1.0f / (3.0f * NPIX));
    float m = ((1.f - ss) * 10.f + g_sdtw[t] * (1.f / 500.f)) * 0.5f;
    red[t] = m;
    __syncthreads();
    #pragma unroll
    for (int off = 128; off > 0; off >>= 1) {
        if (t < off) red[t] += red[t + off];
        __syncthreads();
    }
    if (t == 0) ms_sh = red[0] / (float)S_SZ;   // metric_sum = sum_b mean_s
    __syncthreads();

    // BCE (torch semantics: log clamped at -100)
    float bt = 0.f;
    if (t < B_SZ) {
        float o = outp[t], l = labels[t];
        float ln  = fmaxf(logf(o), -100.f);
        float ln1 = fmaxf(log1pf(-o), -100.f);
        bt = l * ln + (1.f - l) * ln1;
    }
    red[t] = bt;
    __syncthreads();
    #pragma unroll
    for (int off = 128; off > 0; off >>= 1) {
        if (t < off) red[t] += red[t + off];
        __syncthreads();
    }

    // zero any extra poisoned output slots
    for (int i = t; i < out_size; i += blockDim.x) if (i >= 3) out[i] = 0.f;
    if (t == 0) {
        float bce = -red[0] / (float)B_SZ;
        float metric_sum = ms_sh;
        float loss = bce + metric_sum * 0.1f;
        if (out_size >= 1) out[0] = loss;
        if (out_size >= 2) out[1] = bce;
        if (out_size >= 3) out[2] = metric_sum;
    }
}

extern "C" void kernel_launch(void* const* d_in, const int* in_sizes, int n_in,
                              void* d_out, int out_size) {
    (void)in_sizes; (void)n_in;
    const float* input   = (const float*)d_in[0];  // [32,256]
    const float* samples = (const float*)d_in[1];  // [8,256]
    const float* img     = (const float*)d_in[2];  // [32,3,128,128]
    const float* simg    = (const float*)d_in[3];  // [8,3,128,128]
    const float* outp    = (const float*)d_in[4];  // [32,1]
    const float* labels  = (const float*)d_in[5];  // [32,1]
    float* out = (float*)d_out;

    const int smemA = (IMG_H*IMG_W + 2 * IMG_H*OUT_W) * (int)sizeof(float); // 186368
    const int smemB = (IMG_H*IMG_W +     IMG_H*OUT_W) * (int)sizeof(float); // 125952
    cudaFuncSetAttribute(stats_kernel, cudaFuncAttributeMaxDynamicSharedMemorySize, smemA);
    cudaFuncSetAttribute(ssim_kernel,  cudaFuncAttributeMaxDynamicSharedMemorySize, smemB);

    stats_kernel   <<<NIMG * 3, 256, smemA>>>(img, simg);
    ssim_kernel    <<<NPAIR * 3, 256, smemB>>>(img, simg);
    sdtw_kernel    <<<NPAIR, T_SZ>>>(input, samples);
    finalize_kernel<<<1, 256>>>(outp, labels, out, out_size);
}

// round 13
// speedup vs baseline: 1.0090x; 1.0090x over previous
#include <cuda_runtime.h>
#include <math.h>

#define B_SZ 32
#define S_SZ 8
#define T_SZ 256
#define IMG_H 128
#define IMG_W 128
#define KS 11
#define OUT_W 118            // 128 - 11 + 1
#define NPIX (OUT_W*OUT_W)   // 13924
#define NIMG 40              // 32 img + 8 sample_img
#define NPAIR 256            // B*S
#define INFV 1e10f
#define C1V 1.0e-4f
#define C2V 9.0e-4f

// -------- scratch (device globals; no runtime allocation) --------
__device__ float g_mu  [NIMG*3*NPIX];   // blurred mean per image-channel
__device__ float g_sxx [NIMG*3*NPIX];   // blur(x^2) - mu^2 per image-channel
__device__ float g_ssim_part[NPAIR*3];  // per (pair,channel) SSIM pixel-sum
__device__ float g_sdtw[NPAIR];         // soft-DTW result per pair

// Gaussian weights computed in double (matches numpy float64 -> f32 path)
__device__ __forceinline__ void make_weights(float* w, int tid) {
    if (tid == 0) {
        double tmp[KS]; double s = 0.0;
        #pragma unroll
        for (int i = 0; i < KS; i++) {
            double t = (i - 5.0) / 1.5;
            tmp[i] = exp(-0.5 * t * t);
            s += tmp[i];
        }
        #pragma unroll
        for (int i = 0; i < KS; i++) w[i] = (float)(tmp[i] / s);
    }
}

// ================= kernel A: per-image-channel blur stats =================
// grid = NIMG*3 blocks, 256 threads
__global__ void stats_kernel(const float* __restrict__ img,
                             const float* __restrict__ simg) {
    extern __shared__ float sh[];
    float* xbuf = sh;                       // 128*128
    float* t1   = xbuf + IMG_H*IMG_W;       // 128*118  (blur_h(x))
    float* t2   = t1   + IMG_H*OUT_W;       // 128*118  (blur_h(x^2))
    __shared__ float w[KS];
    const int tid = threadIdx.x;
    const int n = blockIdx.x / 3;
    const int c = blockIdx.x % 3;
    make_weights(w, tid);

    const float* src = (n < B_SZ)
        ? (img  + ((size_t)n * 3 + c) * (IMG_H*IMG_W))
        : (simg + ((size_t)(n - B_SZ) * 3 + c) * (IMG_H*IMG_W));

    for (int i = tid; i < IMG_H*IMG_W; i += blockDim.x) xbuf[i] = src[i];
    __syncthreads();

    for (int i = tid; i < IMG_H*OUT_W; i += blockDim.x) {
        int r = i / OUT_W, c0 = i % OUT_W;
        const float* row = xbuf + r * IMG_W + c0;
        float a = 0.f, b = 0.f;
        #pragma unroll
        for (int k = 0; k < KS; k++) {
            float v = row[k];
            a = fmaf(w[k], v, a);
            b = fmaf(w[k], v * v, b);
        }
        t1[i] = a; t2[i] = b;
    }
    __syncthreads();

    float* mu_out  = g_mu  + (size_t)blockIdx.x * NPIX;
    float* sxx_out = g_sxx + (size_t)blockIdx.x * NPIX;
    for (int i = tid; i < NPIX; i += blockDim.x) {
        int r = i / OUT_W, c0 = i % OUT_W;
        float a = 0.f, b = 0.f;
        #pragma unroll
        for (int k = 0; k < KS; k++) {
            a = fmaf(w[k], t1[(r + k) * OUT_W + c0], a);
            b = fmaf(w[k], t2[(r + k) * OUT_W + c0], b);
        }
        mu_out[i]  = a;
        sxx_out[i] = b - a * a;
    }
}

// ================= kernel B: per-pair cross blur + SSIM sum =================
// grid = NPAIR*3 blocks, 256 threads. Only blur(x*y) is pair-dependent.
__global__ void ssim_kernel(const float* __restrict__ img,
                            const float* __restrict__ simg) {
    extern __shared__ float sh[];
    float* prod = sh;                     // 128*128
    float* t1   = prod + IMG_H*IMG_W;     // 128*118
    __shared__ float w[KS];
    __shared__ float red[256];
    const int tid = threadIdx.x;
    const int p = blockIdx.x / 3;         // pair index b*S + s
    const int c = blockIdx.x % 3;
    const int b = p / S_SZ;
    const int s = p % S_SZ;
    make_weights(w, tid);

    const float* x = simg + ((size_t)s * 3 + c) * (IMG_H*IMG_W); // X = sample
    const float* y = img  + ((size_t)b * 3 + c) * (IMG_H*IMG_W); // Y = img
    for (int i = tid; i < IMG_H*IMG_W; i += blockDim.x) prod[i] = x[i] * y[i];
    __syncthreads();

    for (int i = tid; i < IMG_H*OUT_W; i += blockDim.x) {
        int r = i / OUT_W, c0 = i % OUT_W;
        const float* row = prod + r * IMG_W + c0;
        float a = 0.f;
        #pragma unroll
        for (int k = 0; k < KS; k++) a = fmaf(w[k], row[k], a);
        t1[i] = a;
    }
    __syncthreads();

    const float* mux_p = g_mu  + (size_t)((B_SZ + s) * 3 + c) * NPIX;
    const float* muy_p = g_mu  + (size_t)(b * 3 + c) * NPIX;
    const float* sxx_p = g_sxx + (size_t)((B_SZ + s) * 3 + c) * NPIX;
    const float* syy_p = g_sxx + (size_t)(b * 3 + c) * NPIX;

    float acc = 0.f;
    for (int i = tid; i < NPIX; i += blockDim.x) {
        int r = i / OUT_W, c0 = i % OUT_W;
        float sb = 0.f;
        #pragma unroll
        for (int k = 0; k < KS; k++) sb = fmaf(w[k], t1[(r + k) * OUT_W + c0], sb);
        float mx = mux_p[i], my = muy_p[i];
        float mxy = mx * my;
        float sxy = sb - mxy;
        float num = (2.f * mxy + C1V) * (2.f * sxy + C2V);
        float den = (mx * mx + my * my + C1V) * (sxx_p[i] + syy_p[i] + C2V);
        acc += num / den;
    }
    red[tid] = acc;
    __syncthreads();
    #pragma unroll
    for (int off = 128; off > 0; off >>= 1) {
        if (tid < off) red[tid] += red[tid + off];
        __syncthreads();
    }
    if (tid == 0) g_ssim_part[blockIdx.x] = red[0];
}

// ================= kernel C: soft-DTW wavefront =================
// grid = NPAIR blocks, T_SZ threads. thread i owns row i; anti-diagonal sweep.
__global__ void sdtw_kernel(const float* __restrict__ input,
                            const float* __restrict__ samples) {
    __shared__ float ybuf[T_SZ];
    __shared__ float diag[3][T_SZ + 1];
    const int p = blockIdx.x;
    const int b = p / S_SZ;
    const int s = p % S_SZ;
    const int i = threadIdx.x;

    const float xi = input[b * T_SZ + i];
    ybuf[i] = samples[s * T_SZ + i];
    diag[0][i] = INFV; diag[1][i] = INFV; diag[2][i] = INFV;
    if (i == 0) { diag[0][T_SZ] = INFV; diag[1][T_SZ] = INFV; diag[2][T_SZ] = INFV; }
    __syncthreads();

    float myPrev = INFV;   // R[i, j-1] = my value from previous diagonal
    #pragma unroll 1
    for (int k = 0; k < 2 * T_SZ - 1; k++) {
        const int cur = k % 3;            // diag k
        const int p1  = (k + 2) % 3;      // diag k-1
        const int p2  = (k + 1) % 3;      // diag k-2
        const int j = k - i;
        const float a  = diag[p2][i];     // R[i-1, j-1]
        const float bb = diag[p1][i];     // R[i-1, j]
        const float cc = myPrev;          // R[i, j-1]
        float m = fminf(fminf(a, bb), cc);
        float e = __expf((m - a) * 100.f) + __expf((m - bb) * 100.f)
                + __expf((m - cc) * 100.f);
        float sm = m - 0.01f * __logf(e);
        if (k == 0 && i == 0) sm = 0.f;   // base cell R[0,0] = D[0,0]
        float r;
        if (j >= 0 && j < T_SZ) {
            float d = xi - ybuf[j];
            r = fmaf(d, d, sm);
        } else {
            r = INFV;
        }
        diag[cur][i + 1] = r;
        myPrev = r;
        __syncthreads();
    }
    if (i == T_SZ - 1) g_sdtw[p] = myPrev;  // R[T-1, T-1]
}

// ================= kernel D: finalize (metric sum + BCE + loss) =================
__global__ void finalize_kernel(const float* __restrict__ outp,
                                const float* __restrict__ labels,
                                float* __restrict__ out, int out_size) {
    __shared__ float red[256];
    __shared__ float ms_sh;
    const int t = threadIdx.x;

    // per-pair metric: ((1-ssim)*10 + sdtw/500) / 2
    float ss = (g_ssim_part[t * 3] + g_ssim_part[t * 3 + 1] + g_ssim_part[t * 3 + 2])
               * (1.0f / (3.0f * NPIX));
    float m = ((1.f - ss) * 10.f + g_sdtw[t] * (1.f / 500.f)) * 0.5f;
    red[t] = m;
    __syncthreads();
    #pragma unroll
    for (int off = 128; off > 0; off >>= 1) {
        if (t < off) red[t] += red[t + off];
        __syncthreads();
    }
    if (t == 0) ms_sh = red[0] / (float)S_SZ;   // metric_sum = sum_b mean_s
    __syncthreads();

    // BCE (torch semantics: log clamped at -100)
    float bt = 0.f;
    if (t < B_SZ) {
        float o = outp[t], l = labels[t];
        float ln  = fmaxf(logf(o), -100.f);
        float ln1 = fmaxf(log1pf(-o), -100.f);
        bt = l * ln + (1.f - l) * ln1;
    }
    red[t] = bt;
    __syncthreads();
    #pragma unroll
    for (int off = 128; off > 0; off >>= 1) {
        if (t < off) red[t] += red[t + off];
        __syncthreads();
    }

    // zero any extra poisoned output slots
    for (int i = t; i < out_size; i += blockDim.x) if (i >= 3) out[i] = 0.f;
    if (t == 0) {
        float bce = -red[0] / (float)B_SZ;
        float metric_sum = ms_sh;
        float loss = bce + metric_sum * 0.1f;
        if (out_size >= 1) out[0] = loss;
        if (out_size >= 2) out[1] = bce;
        if (out_size >= 3) out[2] = metric_sum;
    }
}

extern "C" void kernel_launch(void* const* d_in, const int* in_sizes, int n_in,
                              void* d_out, int out_size) {
    (void)in_sizes; (void)n_in;
    const float* input   = (const float*)d_in[0];  // [32,256]
    const float* samples = (const float*)d_in[1];  // [8,256]
    const float* img     = (const float*)d_in[2];  // [32,3,128,128]
    const float* simg    = (const float*)d_in[3];  // [8,3,128,128]
    const float* outp    = (const float*)d_in[4];  // [32,1]
    const float* labels  = (const float*)d_in[5];  // [32,1]
    float* out = (float*)d_out;

    const int smemA = (IMG_H*IMG_W + 2 * IMG_H*OUT_W) * (int)sizeof(float); // 186368
    const int smemB = (IMG_H*IMG_W +     IMG_H*OUT_W) * (int)sizeof(float); // 125952
    cudaFuncSetAttribute(stats_kernel, cudaFuncAttributeMaxDynamicSharedMemorySize, smemA);
    cudaFuncSetAttribute(ssim_kernel,  cudaFuncAttributeMaxDynamicSharedMemorySize, smemB);

    stats_kernel   <<<NIMG * 3, 256, smemA>>>(img, simg);
    ssim_kernel    <<<NPAIR * 3, 256, smemB>>>(img, simg);
    sdtw_kernel    <<<NPAIR, T_SZ>>>(input, samples);
    finalize_kernel<<<1, 256>>>(outp, labels, out, out_size);
}

// round 14
// speedup vs baseline: 1.0122x; 1.0031x over previous
#include <cuda_runtime.h>
#include <math.h>

#define B_SZ 32
#define S_SZ 8
#define T_SZ 256
#define IMG_H 128
#define IMG_W 128
#define KS 11
#define OUT_W 118            // 128 - 11 + 1
#define NPIX (OUT_W*OUT_W)   // 13924
#define NIMG 40              // 32 img + 8 sample_img
#define NPAIR 256            // B*S
#define INFV 1e10f
#define C1V 1.0e-4f
#define C2V 9.0e-4f

// -------- scratch (device globals; no runtime allocation) --------
__device__ float g_mu  [NIMG*3*NPIX];   // blurred mean per image-channel
__device__ float g_sxx [NIMG*3*NPIX];   // blur(x^2) - mu^2 per image-channel
__device__ float g_ssim_part[NPAIR*3];  // per (pair,channel) SSIM pixel-sum
__device__ float g_sdtw[NPAIR];         // soft-DTW result per pair

// Gaussian weights computed in double (matches numpy float64 -> f32 path)
__device__ __forceinline__ void make_weights(float* w, int tid) {
    if (tid == 0) {
        double tmp[KS]; double s = 0.0;
        #pragma unroll
        for (int i = 0; i < KS; i++) {
            double t = (i - 5.0) / 1.5;
            tmp[i] = exp(-0.5 * t * t);
            s += tmp[i];
        }
        #pragma unroll
        for (int i = 0; i < KS; i++) w[i] = (float)(tmp[i] / s);
    }
}

// ================= kernel A: per-image-channel blur stats =================
// grid = NIMG*3 blocks, 256 threads
__global__ void stats_kernel(const float* __restrict__ img,
                             const float* __restrict__ simg) {
    extern __shared__ float sh[];
    float* xbuf = sh;                       // 128*128
    float* t1   = xbuf + IMG_H*IMG_W;       // 128*118  (blur_h(x))
    float* t2   = t1   + IMG_H*OUT_W;       // 128*118  (blur_h(x^2))
    __shared__ float w[KS];
    const int tid = threadIdx.x;
    const int n = blockIdx.x / 3;
    const int c = blockIdx.x % 3;
    make_weights(w, tid);

    const float* src = (n < B_SZ)
        ? (img  + ((size_t)n * 3 + c) * (IMG_H*IMG_W))
        : (simg + ((size_t)(n - B_SZ) * 3 + c) * (IMG_H*IMG_W));

    for (int i = tid; i < IMG_H*IMG_W; i += blockDim.x) xbuf[i] = src[i];
    __syncthreads();

    for (int i = tid; i < IMG_H*OUT_W; i += blockDim.x) {
        int r = i / OUT_W, c0 = i % OUT_W;
        const float* row = xbuf + r * IMG_W + c0;
        float a = 0.f, b = 0.f;
        #pragma unroll
        for (int k = 0; k < KS; k++) {
            float v = row[k];
            a = fmaf(w[k], v, a);
            b = fmaf(w[k], v * v, b);
        }
        t1[i] = a; t2[i] = b;
    }
    __syncthreads();

    float* mu_out  = g_mu  + (size_t)blockIdx.x * NPIX;
    float* sxx_out = g_sxx + (size_t)blockIdx.x * NPIX;
    for (int i = tid; i < NPIX; i += blockDim.x) {
        int r = i / OUT_W, c0 = i % OUT_W;
        float a = 0.f, b = 0.f;
        #pragma unroll
        for (int k = 0; k < KS; k++) {
            a = fmaf(w[k], t1[(r + k) * OUT_W + c0], a);
            b = fmaf(w[k], t2[(r + k) * OUT_W + c0], b);
        }
        mu_out[i]  = a;
        sxx_out[i] = b - a * a;
    }
}

// ================= kernel B: per-pair cross blur + SSIM sum =================
// grid = NPAIR*3 blocks, 256 threads. Only blur(x*y) is pair-dependent.
__global__ void ssim_kernel(const float* __restrict__ img,
                            const float* __restrict__ simg) {
    extern __shared__ float sh[];
    float* prod = sh;                     // 128*128
    float* t1   = prod + IMG_H*IMG_W;     // 128*118
    __shared__ float w[KS];
    __shared__ float red[256];
    const int tid = threadIdx.x;
    const int p = blockIdx.x / 3;         // pair index b*S + s
    const int c = blockIdx.x % 3;
    const int b = p / S_SZ;
    const int s = p % S_SZ;
    make_weights(w, tid);

    const float* x = simg + ((size_t)s * 3 + c) * (IMG_H*IMG_W); // X = sample
    const float* y = img  + ((size_t)b * 3 + c) * (IMG_H*IMG_W); // Y = img
    for (int i = tid; i < IMG_H*IMG_W; i += blockDim.x) prod[i] = x[i] * y[i];
    __syncthreads();

    for (int i = tid; i < IMG_H*OUT_W; i += blockDim.x) {
        int r = i / OUT_W, c0 = i % OUT_W;
        const float* row = prod + r * IMG_W + c0;
        float a = 0.f;
        #pragma unroll
        for (int k = 0; k < KS; k++) a = fmaf(w[k], row[k], a);
        t1[i] = a;
    }
    __syncthreads();

    const float* mux_p = g_mu  + (size_t)((B_SZ + s) * 3 + c) * NPIX;
    const float* muy_p = g_mu  + (size_t)(b * 3 + c) * NPIX;
    const float* sxx_p = g_sxx + (size_t)((B_SZ + s) * 3 + c) * NPIX;
    const float* syy_p = g_sxx + (size_t)(b * 3 + c) * NPIX;

    float acc = 0.f;
    for (int i = tid; i < NPIX; i += blockDim.x) {
        int r = i / OUT_W, c0 = i % OUT_W;
        float sb = 0.f;
        #pragma unroll
        for (int k = 0; k < KS; k++) sb = fmaf(w[k], t1[(r + k) * OUT_W + c0], sb);
        float mx = mux_p[i], my = muy_p[i];
        float mxy = mx * my;
        float sxy = sb - mxy;
        float num = (2.f * mxy + C1V) * (2.f * sxy + C2V);
        float den = (mx * mx + my * my + C1V) * (sxx_p[i] + syy_p[i] + C2V);
        acc += num / den;
    }
    red[tid] = acc;
    __syncthreads();
    #pragma unroll
    for (int off = 128; off > 0; off >>= 1) {
        if (tid < off) red[tid] += red[tid + off];
        __syncthreads();
    }
    if (tid == 0) g_ssim_part[blockIdx.x] = red[0];
}

// ================= kernel C: soft-DTW wavefront =================
// grid = NPAIR blocks, T_SZ threads. thread i owns row i; anti-diagonal sweep.
__global__ void sdtw_kernel(const float* __restrict__ input,
                            const float* __restrict__ samples) {
    __shared__ float ybuf[T_SZ];
    __shared__ float diag[3][T_SZ + 1];
    const int p = blockIdx.x;
    const int b = p / S_SZ;
    const int s = p % S_SZ;
    const int i = threadIdx.x;

    const float xi = input[b * T_SZ + i];
    ybuf[i] = samples[s * T_SZ + i];
    diag[0][i] = INFV; diag[1][i] = INFV; diag[2][i] = INFV;
    if (i == 0) { diag[0][T_SZ] = INFV; diag[1][T_SZ] = INFV; diag[2][T_SZ] = INFV; }
    __syncthreads();

    float myPrev = INFV;   // R[i, j-1] = my value from previous diagonal
    #pragma unroll 1
    for (int k = 0; k < 2 * T_SZ - 1; k++) {
        const int cur = k % 3;            // diag k
        const int p1  = (k + 2) % 3;      // diag k-1
        const int p2  = (k + 1) % 3;      // diag k-2
        const int j = k - i;
        const float a  = diag[p2][i];     // R[i-1, j-1]
        const float bb = diag[p1][i];     // R[i-1, j]
        const float cc = myPrev;          // R[i, j-1]
        float m = fminf(fminf(a, bb), cc);
        float e = __expf((m - a) * 100.f) + __expf((m - bb) * 100.f)
                + __expf((m - cc) * 100.f);
        float sm = m - 0.01f * __logf(e);
        if (k == 0 && i == 0) sm = 0.f;   // base cell R[0,0] = D[0,0]
        float r;
        if (j >= 0 && j < T_SZ) {
            float d = xi - ybuf[j];
            r = fmaf(d, d, sm);
        } else {
            r = INFV;
        }
        diag[cur][i + 1] = r;
        myPrev = r;
        __syncthreads();
    }
    if (i == T_SZ - 1) g_sdtw[p] = myPrev;  // R[T-1, T-1]
}

// ================= kernel D: finalize (metric sum + BCE + loss) =================
__global__ void finalize_kernel(const float* __restrict__ outp,
                                const float* __restrict__ labels,
                                float* __restrict__ out, int out_size) {
    __shared__ float red[256];
    __shared__ float ms_sh;
    const int t = threadIdx.x;

    // per-pair metric: ((1-ssim)*10 + sdtw/500) / 2
    float ss = (g_ssim_part[t * 3] + g_ssim_part[t * 3 + 1] + g_ssim_part[t * 3 + 2])
               * (1.0f / (3.0f * NPIX));
    float m = ((1.f - ss) * 10.f + g_sdtw[t] * (1.f / 500.f)) * 0.5f;
    red[t] = m;
    __syncthreads();
    #pragma unroll
    for (int off = 128; off > 0; off >>= 1) {
        if (t < off) red[t] += red[t + off];
        __syncthreads();
    }
    if (t == 0) ms_sh = red[0] / (float)S_SZ;   // metric_sum = sum_b mean_s
    __syncthreads();

    // BCE (torch semantics: log clamped at -100)
    float bt = 0.f;
    if (t < B_SZ) {
        float o = outp[t], l = labels[t];
        float ln  = fmaxf(logf(o), -100.f);
        float ln1 = fmaxf(log1pf(-o), -100.f);
        bt = l * ln + (1.f - l) * ln1;
    }
    red[t] = bt;
    __syncthreads();
    #pragma unroll
    for (int off = 128; off > 0; off >>= 1) {
        if (t < off) red[t] += red[t + off];
        __syncthreads();
    }

    // zero any extra poisoned output slots
    for (int i = t; i < out_size; i += blockDim.x) if (i >= 3) out[i] = 0.f;
    if (t == 0) {
        float bce = -red[0] / (float)B_SZ;
        float metric_sum = ms_sh;
        float loss = bce + metric_sum * 0.1f;
        if (out_size >= 1) out[0] = loss;
        if (out_size >= 2) out[1] = bce;
        if (out_size >= 3) out[2] = metric_sum;
    }
}

extern "C" void kernel_launch(void* const* d_in, const int* in_sizes, int n_in,
                              void* d_out, int out_size) {
    (void)in_sizes; (void)n_in;
    const float* input   = (const float*)d_in[0];  // [32,256]
    const float* samples = (const float*)d_in[1];  // [8,256]
    const float* img     = (const float*)d_in[2];  // [32,3,128,128]
    const float* simg    = (const float*)d_in[3];  // [8,3,128,128]
    const float* outp    = (const float*)d_in[4];  // [32,1]
    const float* labels  = (const float*)d_in[5];  // [32,1]
    float* out = (float*)d_out;

    const int smemA = (IMG_H*IMG_W + 2 * IMG_H*OUT_W) * (int)sizeof(float); // 186368
    const int smemB = (IMG_H*IMG_W +     IMG_H*OUT_W) * (int)sizeof(float); // 125952
    cudaFuncSetAttribute(stats_kernel, cudaFuncAttributeMaxDynamicSharedMemorySize, smemA);
    cudaFuncSetAttribute(ssim_kernel,  cudaFuncAttributeMaxDynamicSharedMemorySize, smemB);

    stats_kernel   <<<NIMG * 3, 256, smemA>>>(img, simg);
    ssim_kernel    <<<NPAIR * 3, 256, smemB>>>(img, simg);
    sdtw_kernel    <<<NPAIR, T_SZ>>>(input, samples);
    finalize_kernel<<<1, 256>>>(outp, labels, out, out_size);
}

// round 15
// speedup vs baseline: 1.0130x; 1.0008x over previous
#include <cuda_runtime.h>
#include <math.h>

#define B_SZ 32
#define S_SZ 8
#define T_SZ 256
#define IMG_H 128
#define IMG_W 128
#define KS 11
#define OUT_W 118            // 128 - 11 + 1
#define NPIX (OUT_W*OUT_W)   // 13924
#define NIMG 40              // 32 img + 8 sample_img
#define NPAIR 256            // B*S
#define INFV 1e10f
#define C1V 1.0e-4f
#define C2V 9.0e-4f

// -------- scratch (device globals; no runtime allocation) --------
__device__ float g_mu  [NIMG*3*NPIX];   // blurred mean per image-channel
__device__ float g_sxx [NIMG*3*NPIX];   // blur(x^2) - mu^2 per image-channel
__device__ float g_ssim_part[NPAIR*3];  // per (pair,channel) SSIM pixel-sum
__device__ float g_sdtw[NPAIR];         // soft-DTW result per pair

// Gaussian weights computed in double (matches numpy float64 -> f32 path)
__device__ __forceinline__ void make_weights(float* w, int tid) {
    if (tid == 0) {
        double tmp[KS]; double s = 0.0;
        #pragma unroll
        for (int i = 0; i < KS; i++) {
            double t = (i - 5.0) / 1.5;
            tmp[i] = exp(-0.5 * t * t);
            s += tmp[i];
        }
        #pragma unroll
        for (int i = 0; i < KS; i++) w[i] = (float)(tmp[i] / s);
    }
}

// ================= kernel A: per-image-channel blur stats =================
// grid = NIMG*3 blocks, 256 threads
__global__ void stats_kernel(const float* __restrict__ img,
                             const float* __restrict__ simg) {
    extern __shared__ float sh[];
    float* xbuf = sh;                       // 128*128
    float* t1   = xbuf + IMG_H*IMG_W;       // 128*118  (blur_h(x))
    float* t2   = t1   + IMG_H*OUT_W;       // 128*118  (blur_h(x^2))
    __shared__ float w[KS];
    const int tid = threadIdx.x;
    const int n = blockIdx.x / 3;
    const int c = blockIdx.x % 3;
    make_weights(w, tid);

    const float* src = (n < B_SZ)
        ? (img  + ((size_t)n * 3 + c) * (IMG_H*IMG_W))
        : (simg + ((size_t)(n - B_SZ) * 3 + c) * (IMG_H*IMG_W));

    for (int i = tid; i < IMG_H*IMG_W; i += blockDim.x) xbuf[i] = src[i];
    __syncthreads();

    for (int i = tid; i < IMG_H*OUT_W; i += blockDim.x) {
        int r = i / OUT_W, c0 = i % OUT_W;
        const float* row = xbuf + r * IMG_W + c0;
        float a = 0.f, b = 0.f;
        #pragma unroll
        for (int k = 0; k < KS; k++) {
            float v = row[k];
            a = fmaf(w[k], v, a);
            b = fmaf(w[k], v * v, b);
        }
        t1[i] = a; t2[i] = b;
    }
    __syncthreads();

    float* mu_out  = g_mu  + (size_t)blockIdx.x * NPIX;
    float* sxx_out = g_sxx + (size_t)blockIdx.x * NPIX;
    for (int i = tid; i < NPIX; i += blockDim.x) {
        int r = i / OUT_W, c0 = i % OUT_W;
        float a = 0.f, b = 0.f;
        #pragma unroll
        for (int k = 0; k < KS; k++) {
            a = fmaf(w[k], t1[(r + k) * OUT_W + c0], a);
            b = fmaf(w[k], t2[(r + k) * OUT_W + c0], b);
        }
        mu_out[i]  = a;
        sxx_out[i] = b - a * a;
    }
}

// ================= kernel B: per-pair cross blur + SSIM sum =================
// grid = NPAIR*3 blocks, 256 threads. Only blur(x*y) is pair-dependent.
__global__ void ssim_kernel(const float* __restrict__ img,
                            const float* __restrict__ simg) {
    extern __shared__ float sh[];
    float* prod = sh;                     // 128*128
    float* t1   = prod + IMG_H*IMG_W;     // 128*118
    __shared__ float w[KS];
    __shared__ float red[256];
    const int tid = threadIdx.x;
    const int p = blockIdx.x / 3;         // pair index b*S + s
    const int c = blockIdx.x % 3;
    const int b = p / S_SZ;
    const int s = p % S_SZ;
    make_weights(w, tid);

    const float* x = simg + ((size_t)s * 3 + c) * (IMG_H*IMG_W); // X = sample
    const float* y = img  + ((size_t)b * 3 + c) * (IMG_H*IMG_W); // Y = img
    for (int i = tid; i < IMG_H*IMG_W; i += blockDim.x) prod[i] = x[i] * y[i];
    __syncthreads();

    for (int i = tid; i < IMG_H*OUT_W; i += blockDim.x) {
        int r = i / OUT_W, c0 = i % OUT_W;
        const float* row = prod + r * IMG_W + c0;
        float a = 0.f;
        #pragma unroll
        for (int k = 0; k < KS; k++) a = fmaf(w[k], row[k], a);
        t1[i] = a;
    }
    __syncthreads();

    const float* mux_p = g_mu  + (size_t)((B_SZ + s) * 3 + c) * NPIX;
    const float* muy_p = g_mu  + (size_t)(b * 3 + c) * NPIX;
    const float* sxx_p = g_sxx + (size_t)((B_SZ + s) * 3 + c) * NPIX;
    const float* syy_p = g_sxx + (size_t)(b * 3 + c) * NPIX;

    float acc = 0.f;
    for (int i = tid; i < NPIX; i += blockDim.x) {
        int r = i / OUT_W, c0 = i % OUT_W;
        float sb = 0.f;
        #pragma unroll
        for (int k = 0; k < KS; k++) sb = fmaf(w[k], t1[(r + k) * OUT_W + c0], sb);
        float mx = mux_p[i], my = muy_p[i];
        float mxy = mx * my;
        float sxy = sb - mxy;
        float num = (2.f * mxy + C1V) * (2.f * sxy + C2V);
        float den = (mx * mx + my * my + C1V) * (sxx_p[i] + syy_p[i] + C2V);
        acc += num / den;
    }
    red[tid] = acc;
    __syncthreads();
    #pragma unroll
    for (int off = 128; off > 0; off >>= 1) {
        if (tid < off) red[tid] += red[tid + off];
        __syncthreads();
    }
    if (tid == 0) g_ssim_part[blockIdx.x] = red[0];
}

// ================= kernel C: soft-DTW wavefront =================
// grid = NPAIR blocks, T_SZ threads. thread i owns row i; anti-diagonal sweep.
__global__ void sdtw_kernel(const float* __restrict__ input,
                            const float* __restrict__ samples) {
    __shared__ float ybuf[T_SZ];
    __shared__ float diag[3][T_SZ + 1];
    const int p = blockIdx.x;
    const int b = p / S_SZ;
    const int s = p % S_SZ;
    const int i = threadIdx.x;

    const float xi = input[b * T_SZ + i];
    ybuf[i] = samples[s * T_SZ + i];
    diag[0][i] = INFV; diag[1][i] = INFV; diag[2][i] = INFV;
    if (i == 0) { diag[0][T_SZ] = INFV; diag[1][T_SZ] = INFV; diag[2][T_SZ] = INFV; }
    __syncthreads();

    float myPrev = INFV;   // R[i, j-1] = my value from previous diagonal
    #pragma unroll 1
    for (int k = 0; k < 2 * T_SZ - 1; k++) {
        const int cur = k % 3;            // diag k
        const int p1  = (k + 2) % 3;      // diag k-1
        const int p2  = (k + 1) % 3;      // diag k-2
        const int j = k - i;
        const float a  = diag[p2][i];     // R[i-1, j-1]
        const float bb = diag[p1][i];     // R[i-1, j]
        const float cc = myPrev;          // R[i, j-1]
        float m = fminf(fminf(a, bb), cc);
        float e = __expf((m - a) * 100.f) + __expf((m - bb) * 100.f)
                + __expf((m - cc) * 100.f);
        float sm = m - 0.01f * __logf(e);
        if (k == 0 && i == 0) sm = 0.f;   // base cell R[0,0] = D[0,0]
        float r;
        if (j >= 0 && j < T_SZ) {
            float d = xi - ybuf[j];
            r = fmaf(d, d, sm);
        } else {
            r = INFV;
        }
        diag[cur][i + 1] = r;
        myPrev = r;
        __syncthreads();
    }
    if (i == T_SZ - 1) g_sdtw[p] = myPrev;  // R[T-1, T-1]
}

// ================= kernel D: finalize (metric sum + BCE + loss) =================
__global__ void finalize_kernel(const float* __restrict__ outp,
                                const float* __restrict__ labels,
                                float* __restrict__ out, int out_size) {
    __shared__ float red[256];
    __shared__ float ms_sh;
    const int t = threadIdx.x;

    // per-pair metric: ((1-ssim)*10 + sdtw/500) / 2
    float ss = (g_ssim_part[t * 3] + g_ssim_part[t * 3 + 1] + g_ssim_part[t * 3 + 2])
               * (1.0f / (3.0f * NPIX));
    float m = ((1.f - ss) * 10.f + g_sdtw[t] * (1.f / 500.f)) * 0.5f;
    red[t] = m;
    __syncthreads();
    #pragma unroll
    for (int off = 128; off > 0; off >>= 1) {
        if (t < off) red[t] += red[t + off];
        __syncthreads();
    }
    if (t == 0) ms_sh = red[0] / (float)S_SZ;   // metric_sum = sum_b mean_s
    __syncthreads();

    // BCE (torch semantics: log clamped at -100)
    float bt = 0.f;
    if (t < B_SZ) {
        float o = outp[t], l = labels[t];
        float ln  = fmaxf(logf(o), -100.f);
        float ln1 = fmaxf(log1pf(-o), -100.f);
        bt = l * ln + (1.f - l) * ln1;
    }
    red[t] = bt;
    __syncthreads();
    #pragma unroll
    for (int off = 128; off > 0; off >>= 1) {
        if (t < off) red[t] += red[t + off];
        __syncthreads();
    }

    // zero any extra poisoned output slots
    for (int i = t; i < out_size; i += blockDim.x) if (i >= 3) out[i] = 0.f;
    if (t == 0) {
        float bce = -red[0] / (float)B_SZ;
        float metric_sum = ms_sh;
        float loss = bce + metric_sum * 0.1f;
        if (out_size >= 1) out[0] = loss;
        if (out_size >= 2) out[1] = bce;
        if (out_size >= 3) out[2] = metric_sum;
    }
}

extern "C" void kernel_launch(void* const* d_in, const int* in_sizes, int n_in,
                              void* d_out, int out_size) {
    (void)in_sizes; (void)n_in;
    const float* input   = (const float*)d_in[0];  // [32,256]
    const float* samples = (const float*)d_in[1];  // [8,256]
    const float* img     = (const float*)d_in[2];  // [32,3,128,128]
    const float* simg    = (const float*)d_in[3];  // [8,3,128,128]
    const float* outp    = (const float*)d_in[4];  // [32,1]
    const float* labels  = (const float*)d_in[5];  // [32,1]
    float* out = (float*)d_out;

    const int smemA = (IMG_H*IMG_W + 2 * IMG_H*OUT_W) * (int)sizeof(float); // 186368
    const int smemB = (IMG_H*IMG_W +     IMG_H*OUT_W) * (int)sizeof(float); // 125952
    cudaFuncSetAttribute(stats_kernel, cudaFuncAttributeMaxDynamicSharedMemorySize, smemA);
    cudaFuncSetAttribute(ssim_kernel,  cudaFuncAttributeMaxDynamicSharedMemorySize, smemB);

    stats_kernel   <<<NIMG * 3, 256, smemA>>>(img, simg);
    ssim_kernel    <<<NPAIR * 3, 256, smemB>>>(img, simg);
    sdtw_kernel    <<<NPAIR, T_SZ>>>(input, samples);
    finalize_kernel<<<1, 256>>>(outp, labels, out, out_size);
}

// round 16
// speedup vs baseline: 1.0148x; 1.0018x over previous
#include <cuda_runtime.h>
#include <math.h>

#define B_SZ 32
#define S_SZ 8
#define T_SZ 256
#define IMG_H 128
#define IMG_W 128
#define KS 11
#define OUT_W 118            // 128 - 11 + 1
#define NPIX (OUT_W*OUT_W)   // 13924
#define NIMG 40              // 32 img + 8 sample_img
#define NPAIR 256            // B*S
#define INFV 1e10f
#define C1V 1.0e-4f
#define C2V 9.0e-4f

// -------- scratch (device globals; no runtime allocation) --------
__device__ float g_mu  [NIMG*3*NPIX];   // blurred mean per image-channel
__device__ float g_sxx [NIMG*3*NPIX];   // blur(x^2) - mu^2 per image-channel
__device__ float g_ssim_part[NPAIR*3];  // per (pair,channel) SSIM pixel-sum
__device__ float g_sdtw[NPAIR];         // soft-DTW result per pair

// Gaussian weights computed in double (matches numpy float64 -> f32 path)
__device__ __forceinline__ void make_weights(float* w, int tid) {
    if (tid == 0) {
        double tmp[KS]; double s = 0.0;
        #pragma unroll
        for (int i = 0; i < KS; i++) {
            double t = (i - 5.0) / 1.5;
            tmp[i] = exp(-0.5 * t * t);
            s += tmp[i];
        }
        #pragma unroll
        for (int i = 0; i < KS; i++) w[i] = (float)(tmp[i] / s);
    }
}

// ================= kernel A: per-image-channel blur stats =================
// grid = NIMG*3 blocks, 256 threads
__global__ void stats_kernel(const float* __restrict__ img,
                             const float* __restrict__ simg) {
    extern __shared__ float sh[];
    float* xbuf = sh;                       // 128*128
    float* t1   = xbuf + IMG_H*IMG_W;       // 128*118  (blur_h(x))
    float* t2   = t1   + IMG_H*OUT_W;       // 128*118  (blur_h(x^2))
    __shared__ float w[KS];
    const int tid = threadIdx.x;
    const int n = blockIdx.x / 3;
    const int c = blockIdx.x % 3;
    make_weights(w, tid);

    const float* src = (n < B_SZ)
        ? (img  + ((size_t)n * 3 + c) * (IMG_H*IMG_W))
        : (simg + ((size_t)(n - B_SZ) * 3 + c) * (IMG_H*IMG_W));

    for (int i = tid; i < IMG_H*IMG_W; i += blockDim.x) xbuf[i] = src[i];
    __syncthreads();

    for (int i = tid; i < IMG_H*OUT_W; i += blockDim.x) {
        int r = i / OUT_W, c0 = i % OUT_W;
        const float* row = xbuf + r * IMG_W + c0;
        float a = 0.f, b = 0.f;
        #pragma unroll
        for (int k = 0; k < KS; k++) {
            float v = row[k];
            a = fmaf(w[k], v, a);
            b = fmaf(w[k], v * v, b);
        }
        t1[i] = a; t2[i] = b;
    }
    __syncthreads();

    float* mu_out  = g_mu  + (size_t)blockIdx.x * NPIX;
    float* sxx_out = g_sxx + (size_t)blockIdx.x * NPIX;
    for (int i = tid; i < NPIX; i += blockDim.x) {
        int r = i / OUT_W, c0 = i % OUT_W;
        float a = 0.f, b = 0.f;
        #pragma unroll
        for (int k = 0; k < KS; k++) {
            a = fmaf(w[k], t1[(r + k) * OUT_W + c0], a);
            b = fmaf(w[k], t2[(r + k) * OUT_W + c0], b);
        }
        mu_out[i]  = a;
        sxx_out[i] = b - a * a;
    }
}

// ================= kernel B: per-pair cross blur + SSIM sum =================
// grid = NPAIR*3 blocks, 256 threads. Only blur(x*y) is pair-dependent.
__global__ void ssim_kernel(const float* __restrict__ img,
                            const float* __restrict__ simg) {
    extern __shared__ float sh[];
    float* prod = sh;                     // 128*128
    float* t1   = prod + IMG_H*IMG_W;     // 128*118
    __shared__ float w[KS];
    __shared__ float red[256];
    const int tid = threadIdx.x;
    const int p = blockIdx.x / 3;         // pair index b*S + s
    const int c = blockIdx.x % 3;
    const int b = p / S_SZ;
    const int s = p % S_SZ;
    make_weights(w, tid);

    const float* x = simg + ((size_t)s * 3 + c) * (IMG_H*IMG_W); // X = sample
    const float* y = img  + ((size_t)b * 3 + c) * (IMG_H*IMG_W); // Y = img
    for (int i = tid; i < IMG_H*IMG_W; i += blockDim.x) prod[i] = x[i] * y[i];
    __syncthreads();

    for (int i = tid; i < IMG_H*OUT_W; i += blockDim.x) {
        int r = i / OUT_W, c0 = i % OUT_W;
        const float* row = prod + r * IMG_W + c0;
        float a = 0.f;
        #pragma unroll
        for (int k = 0; k < KS; k++) a = fmaf(w[k], row[k], a);
        t1[i] = a;
    }
    __syncthreads();

    const float* mux_p = g_mu  + (size_t)((B_SZ + s) * 3 + c) * NPIX;
    const float* muy_p = g_mu  + (size_t)(b * 3 + c) * NPIX;
    const float* sxx_p = g_sxx + (size_t)((B_SZ + s) * 3 + c) * NPIX;
    const float* syy_p = g_sxx + (size_t)(b * 3 + c) * NPIX;

    float acc = 0.f;
    for (int i = tid; i < NPIX; i += blockDim.x) {
        int r = i / OUT_W, c0 = i % OUT_W;
        float sb = 0.f;
        #pragma unroll
        for (int k = 0; k < KS; k++) sb = fmaf(w[k], t1[(r + k) * OUT_W + c0], sb);
        float mx = mux_p[i], my = muy_p[i];
        float mxy = mx * my;
        float sxy = sb - mxy;
        float num = (2.f * mxy + C1V) * (2.f * sxy + C2V);
        float den = (mx * mx + my * my + C1V) * (sxx_p[i] + syy_p[i] + C2V);
        acc += num / den;
    }
    red[tid] = acc;
    __syncthreads();
    #pragma unroll
    for (int off = 128; off > 0; off >>= 1) {
        if (tid < off) red[tid] += red[tid + off];
        __syncthreads();
    }
    if (tid == 0) g_ssim_part[blockIdx.x] = red[0];
}

// ================= kernel C: soft-DTW wavefront =================
// grid = NPAIR blocks, T_SZ threads. thread i owns row i; anti-diagonal sweep.
__global__ void sdtw_kernel(const float* __restrict__ input,
                            const float* __restrict__ samples) {
    __shared__ float ybuf[T_SZ];
    __shared__ float diag[3][T_SZ + 1];
    const int p = blockIdx.x;
    const int b = p / S_SZ;
    const int s = p % S_SZ;
    const int i = threadIdx.x;

    const float xi = input[b * T_SZ + i];
    ybuf[i] = samples[s * T_SZ + i];
    diag[0][i] = INFV; diag[1][i] = INFV; diag[2][i] = INFV;
    if (i == 0) { diag[0][T_SZ] = INFV; diag[1][T_SZ] = INFV; diag[2][T_SZ] = INFV; }
    __syncthreads();

    float myPrev = INFV;   // R[i, j-1] = my value from previous diagonal
    #pragma unroll 1
    for (int k = 0; k < 2 * T_SZ - 1; k++) {
        const int cur = k % 3;            // diag k
        const int p1  = (k + 2) % 3;      // diag k-1
        const int p2  = (k + 1) % 3;      // diag k-2
        const int j = k - i;
        const float a  = diag[p2][i];     // R[i-1, j-1]
        const float bb = diag[p1][i];     // R[i-1, j]
        const float cc = myPrev;          // R[i, j-1]
        float m = fminf(fminf(a, bb), cc);
        float e = __expf((m - a) * 100.f) + __expf((m - bb) * 100.f)
                + __expf((m - cc) * 100.f);
        float sm = m - 0.01f * __logf(e);
        if (k == 0 && i == 0) sm = 0.f;   // base cell R[0,0] = D[0,0]
        float r;
        if (j >= 0 && j < T_SZ) {
            float d = xi - ybuf[j];
            r = fmaf(d, d, sm);
        } else {
            r = INFV;
        }
        diag[cur][i + 1] = r;
        myPrev = r;
        __syncthreads();
    }
    if (i == T_SZ - 1) g_sdtw[p] = myPrev;  // R[T-1, T-1]
}

// ================= kernel D: finalize (metric sum + BCE + loss) =================
__global__ void finalize_kernel(const float* __restrict__ outp,
                                const float* __restrict__ labels,
                                float* __restrict__ out, int out_size) {
    __shared__ float red[256];
    __shared__ float ms_sh;
    const int t = threadIdx.x;

    // per-pair metric: ((1-ssim)*10 + sdtw/500) / 2
    float ss = (g_ssim_part[t * 3] + g_ssim_part[t * 3 + 1] + g_ssim_part[t * 3 + 2])
               * (1.0f / (3.0f * NPIX));
    float m = ((1.f - ss) * 10.f + g_sdtw[t] * (1.f / 500.f)) * 0.5f;
    red[t] = m;
    __syncthreads();
    #pragma unroll
    for (int off = 128; off > 0; off >>= 1) {
        if (t < off) red[t] += red[t + off];
        __syncthreads();
    }
    if (t == 0) ms_sh = red[0] / (float)S_SZ;   // metric_sum = sum_b mean_s
    __syncthreads();

    // BCE (torch semantics: log clamped at -100)
    float bt = 0.f;
    if (t < B_SZ) {
        float o = outp[t], l = labels[t];
        float ln  = fmaxf(logf(o), -100.f);
        float ln1 = fmaxf(log1pf(-o), -100.f);
        bt = l * ln + (1.f - l) * ln1;
    }
    red[t] = bt;
    __syncthreads();
    #pragma unroll
    for (int off = 128; off > 0; off >>= 1) {
        if (t < off) red[t] += red[t + off];
        __syncthreads();
    }

    // zero any extra poisoned output slots
    for (int i = t; i < out_size; i += blockDim.x) if (i >= 3) out[i] = 0.f;
    if (t == 0) {
        float bce = -red[0] / (float)B_SZ;
        float metric_sum = ms_sh;
        float loss = bce + metric_sum * 0.1f;
        if (out_size >= 1) out[0] = loss;
        if (out_size >= 2) out[1] = bce;
        if (out_size >= 3) out[2] = metric_sum;
    }
}

extern "C" void kernel_launch(void* const* d_in, const int* in_sizes, int n_in,
                              void* d_out, int out_size) {
    (void)in_sizes; (void)n_in;
    const float* input   = (const float*)d_in[0];  // [32,256]
    const float* samples = (const float*)d_in[1];  // [8,256]
    const float* img     = (const float*)d_in[2];  // [32,3,128,128]
    const float* simg    = (const float*)d_in[3];  // [8,3,128,128]
    const float* outp    = (const float*)d_in[4];  // [32,1]
    const float* labels  = (const float*)d_in[5];  // [32,1]
    float* out = (float*)d_out;

    const int smemA = (IMG_H*IMG_W + 2 * IMG_H*OUT_W) * (int)sizeof(float); // 186368
    const int smemB = (IMG_H*IMG_W +     IMG_H*OUT_W) * (int)sizeof(float); // 125952
    cudaFuncSetAttribute(stats_kernel, cudaFuncAttributeMaxDynamicSharedMemorySize, smemA);
    cudaFuncSetAttribute(ssim_kernel,  cudaFuncAttributeMaxDynamicSharedMemorySize, smemB);

    stats_kernel   <<<NIMG * 3, 256, smemA>>>(img, simg);
    ssim_kernel    <<<NPAIR * 3, 256, smemB>>>(img, simg);
    sdtw_kernel    <<<NPAIR, T_SZ>>>(input, samples);
    finalize_kernel<<<1, 256>>>(outp, labels, out, out_size);
}